// round 6
// baseline (speedup 1.0000x reference)
#include <cuda_runtime.h>
#include <cuda_bf16.h>

// text [SEQ=200, BATCH=4096] int32 (row-major text[s*BATCH+b]),
// w [V=50000] f32, bias [1] f32.  out[b] = sum_{unique t in doc b} w[t] + bias.
//
// R6: R5's profile showed L1 wavefronts split ~200 text + ~197 gather per
// block; the text cost is pure layout (stride-16KB column reads, 1 line per
// lane). Kernel 1 transposes text into a __device__ scratch [BATCH, SEQ]
// (both sides coalesced, L2-resident, ~1us); kernel 2 then reads each doc's
// 200 tokens from 7 contiguous lines instead of 200. Dedup = R5's two-level
// byte-store race (collision scan reached ~1 block/launch).

#define SEQ   200
#define BATCH 4096
#define HBITS 13
#define HSIZE (1 << HBITS)   // 8192 byte slots = 8KB

__device__ int g_textT[BATCH * SEQ];   // transposed text, [BATCH, SEQ]

// ── Kernel 1: 32x32 tiled transpose, [SEQ, BATCH] -> [BATCH, SEQ] ──
__global__ __launch_bounds__(256)
void MNB_transpose_kernel(const int* __restrict__ text)
{
    __shared__ int tile[32][33];                 // +1 pad: conflict-free
    const int bb = blockIdx.x * 32;              // batch tile base
    const int bs = blockIdx.y * 32;              // seq tile base
    const int tx = threadIdx.x & 31;
    const int ty = threadIdx.x >> 5;             // 0..7

    #pragma unroll
    for (int r = ty; r < 32; r += 8) {
        const int s = bs + r;
        if (s < SEQ) tile[r][tx] = text[s * BATCH + bb + tx];
    }
    __syncthreads();

    #pragma unroll
    for (int r = ty; r < 32; r += 8) {
        const int s = bs + tx;
        if (s < SEQ) g_textT[(bb + r) * SEQ + s] = tile[tx][r];
    }
}

// ── Kernel 2: per-doc dedup + gather + reduce (R5 structure) ──
__global__ __launch_bounds__(256, 8)
void MNB_24111946400019_kernel(const float* __restrict__ w,
                               const float* __restrict__ bias,
                               float* __restrict__ out)
{
    __shared__ int           toks[SEQ];
    __shared__ unsigned char marker[HSIZE];
    __shared__ float         warp_sums[8];

    const int b   = blockIdx.x;
    const int tid = threadIdx.x;

    // Init marker to 0xFF (real tids are 0..199) with int4 stores: 8KB.
    {
        int4* m4 = reinterpret_cast<int4*>(marker);
        const int4 ff = make_int4(-1, -1, -1, -1);
        m4[tid]       = ff;
        m4[tid + 256] = ff;
    }

    int t = 0;
    unsigned h1 = 0, h2 = 0;
    if (tid < SEQ) {
        t = g_textT[b * SEQ + tid];              // contiguous: ~7 lines/doc
        toks[tid] = t;
        h1 = ((unsigned)t * 2654435761u) >> (32 - HBITS);
        h2 = ((unsigned)t * 0x85EBCA77u) >> (32 - HBITS);
    }
    __syncthreads();

    // Level 1: racing byte store, one winner per slot.
    if (tid < SEQ) marker[h1] = (unsigned char)tid;
    __syncthreads();

    int state = 0;                      // 0=drop, 1=contribute, 2=unresolved
    if (tid < SEQ) {
        const int m = marker[h1];
        if (toks[m] == t) state = (m == tid) ? 1 : 0;
        else              state = 2;    // different-token collision (~2.4/blk)
    }
    __syncthreads();                    // level-1 reads done before level-2 stores

    // Level 2: re-race unresolved under h2 (same table; stale entries provably
    // never match an unresolved thread's token).
    if (state == 2) marker[h2] = (unsigned char)tid;
    __syncthreads();

    float v = 0.0f;
    if (tid < SEQ) {
        if (state == 2) {
            const int m = marker[h2];
            if (toks[m] == t) {
                state = (m == tid) ? 1 : 0;
            } else {
                // Level 3 (≈1 block/launch): exact first-occurrence scan.
                int f = 0;
                while (toks[f] != t) ++f;
                state = (f == tid) ? 1 : 0;
            }
        }
        if (state == 1) v = __ldg(&w[t]);
    }

    // Block reduction (8 warps)
    #pragma unroll
    for (int o = 16; o > 0; o >>= 1)
        v += __shfl_down_sync(0xffffffffu, v, o);
    if ((tid & 31) == 0) warp_sums[tid >> 5] = v;
    __syncthreads();

    if (tid < 32) {
        float s = (tid < 8) ? warp_sums[tid] : 0.0f;
        #pragma unroll
        for (int o = 4; o > 0; o >>= 1)
            s += __shfl_down_sync(0xffffffffu, s, o);
        if (tid == 0) out[b] = s + bias[0];
    }
}

extern "C" void kernel_launch(void* const* d_in, const int* in_sizes, int n_in,
                              void* d_out, int out_size)
{
    const int*   text = (const int*)d_in[0];
    const float* w    = (const float*)d_in[1];
    const float* bias = (const float*)d_in[2];
    float*       out  = (float*)d_out;

    dim3 tgrid(BATCH / 32, (SEQ + 31) / 32);     // 128 x 7
    MNB_transpose_kernel<<<tgrid, 256>>>(text);
    MNB_24111946400019_kernel<<<BATCH, 256>>>(w, bias, out);
}

// round 7
// speedup vs baseline: 1.0173x; 1.0173x over previous
#include <cuda_runtime.h>
#include <cuda_bf16.h>

// text [SEQ=200, BATCH=4096] int32 (row-major text[s*BATCH+b]),
// w [V=50000] f32, bias [1] f32.  out[b] = sum_{unique t in doc b} w[t] + bias.
//
// R7: single kernel, 8 docs per 512-thread block.
//  - Text coalescing without a transpose: item i=s*8+d -> 8 adjacent docs share
//    each 32B sector (25 text wavefronts/doc vs 200 in R5), and the transpose
//    kernel + launch gap (~2.9us in R6) disappears.
//  - Dedup: R5's two-level racing byte store, per-doc 4096-slot tables (32KB).
//    Phase barriers are shared by all 8 docs (8x amortization).
//  - Each thread serves exactly one doc (512 % 8 == 0), ~3.1 gathers issued
//    back-to-back -> MLP hides L2 latency.

#define SEQ    200
#define BATCH  4096
#define DOCS   8                  // docs per block
#define NTHR   512
#define NITEM  (SEQ * DOCS)       // 1600
#define HBITS  12
#define HSIZE  (1 << HBITS)       // 4096 slots per doc

__global__ __launch_bounds__(NTHR, 4)
void MNB_24111946400019_kernel(const int* __restrict__ text,
                               const float* __restrict__ w,
                               const float* __restrict__ bias,
                               float* __restrict__ out)
{
    __shared__ int           toks[DOCS * SEQ];          // [d][s]
    __shared__ unsigned char marker[DOCS * HSIZE];      // 32KB, [d][h]
    __shared__ float         part[DOCS][17];            // per-doc warp partials

    const int b0  = blockIdx.x * DOCS;
    const int tid = threadIdx.x;
    const int d   = tid & 7;                 // this thread's doc (constant: 512%8==0)
    const int dt  = d * SEQ;                 // toks base
    const int dm  = d * HSIZE;               // marker base

    // Init markers to 0xFF (seq idx 0..199 < 255) with int4 stores: 2048 int4s.
    {
        int4* m4 = reinterpret_cast<int4*>(marker);
        const int4 ff = make_int4(-1, -1, -1, -1);
        #pragma unroll
        for (int k = 0; k < (DOCS * HSIZE / 16) / NTHR; ++k)   // 4
            m4[tid + k * NTHR] = ff;
    }

    // Load text: item i = s*8 + d  ->  addr = s*BATCH + b0 + d (32B per 8 lanes).
    int tt[4];
    #pragma unroll
    for (int k = 0; k < 4; ++k) {
        const int i = tid + k * NTHR;
        if (i < NITEM) {
            const int s = i >> 3;
            const int t = text[s * BATCH + b0 + d];
            toks[dt + s] = t;
            tt[k] = t;
        } else tt[k] = -1;
    }
    __syncthreads();

    // ── Level 1: racing byte store per doc-table ──
    #pragma unroll
    for (int k = 0; k < 4; ++k) {
        const int i = tid + k * NTHR;
        if (i < NITEM) {
            const unsigned h1 = ((unsigned)tt[k] * 2654435761u) >> (32 - HBITS);
            marker[dm + h1] = (unsigned char)(i >> 3);
        }
    }
    __syncthreads();

    int st[4];                               // 0=drop, 1=contribute, 2=unresolved
    #pragma unroll
    for (int k = 0; k < 4; ++k) {
        st[k] = 0;
        const int i = tid + k * NTHR;
        if (i < NITEM) {
            const int s = i >> 3;
            const unsigned h1 = ((unsigned)tt[k] * 2654435761u) >> (32 - HBITS);
            const int m = marker[dm + h1];
            if (toks[dt + m] == tt[k]) st[k] = (m == s) ? 1 : 0;
            else                       st[k] = 2;
        }
    }
    __syncthreads();                          // level-1 reads before level-2 stores

    // ── Level 2: unresolved re-race under h2 in the same table ──
    #pragma unroll
    for (int k = 0; k < 4; ++k) {
        if (st[k] == 2) {
            const int i = tid + k * NTHR;
            const unsigned h2 = ((unsigned)tt[k] * 0x85EBCA77u) >> (32 - HBITS);
            marker[dm + h2] = (unsigned char)(i >> 3);
        }
    }
    __syncthreads();

    float v = 0.0f;
    #pragma unroll
    for (int k = 0; k < 4; ++k) {
        const int i = tid + k * NTHR;
        if (i < NITEM && st[k] != 0) {
            const int s = i >> 3;
            int c = st[k];
            if (c == 2) {
                const unsigned h2 = ((unsigned)tt[k] * 0x85EBCA77u) >> (32 - HBITS);
                const int m = marker[dm + h2];
                if (toks[dt + m] == tt[k]) {
                    c = (m == s) ? 1 : 0;
                } else {
                    // Level 3 (~9% of blocks, 1 item): exact first-occurrence scan.
                    int f = 0;
                    while (toks[dt + f] != tt[k]) ++f;   // terminates at f==s
                    c = (f == s) ? 1 : 0;
                }
            }
            if (c == 1) v += __ldg(&w[tt[k]]);
        }
    }

    // ── Per-doc reduction ──
    // Lanes with equal (lane&7) belong to the same doc: xor-16 then xor-8
    // folds the warp to 8 per-doc partials in lanes 0..7.
    v += __shfl_xor_sync(0xffffffffu, v, 16);
    v += __shfl_xor_sync(0xffffffffu, v, 8);
    if ((tid & 31) < 8) part[d][tid >> 5] = v;           // 16 warps
    __syncthreads();

    if (tid < 128) {                                     // 4 full warps
        const int dd = tid >> 4;                         // doc
        const int j  = tid & 15;                         // warp slot
        float s = part[dd][j];
        s += __shfl_xor_sync(0xffffffffu, s, 8);
        s += __shfl_xor_sync(0xffffffffu, s, 4);
        s += __shfl_xor_sync(0xffffffffu, s, 2);
        s += __shfl_xor_sync(0xffffffffu, s, 1);
        if (j == 0) out[b0 + dd] = s + bias[0];
    }
}

extern "C" void kernel_launch(void* const* d_in, const int* in_sizes, int n_in,
                              void* d_out, int out_size)
{
    const int*   text = (const int*)d_in[0];
    const float* w    = (const float*)d_in[1];
    const float* bias = (const float*)d_in[2];
    float*       out  = (float*)d_out;

    MNB_24111946400019_kernel<<<BATCH / DOCS, NTHR>>>(text, w, bias, out);
}

// round 8
// speedup vs baseline: 1.3732x; 1.3499x over previous
#include <cuda_runtime.h>
#include <cuda_bf16.h>

// text [SEQ=200, BATCH=4096] int32 (row-major text[s*BATCH+b]),
// w [V=50000] f32, bias [1] f32.  out[b] = sum_{unique t in doc b} w[t] + bias.
//
// R8: R7 + (a) SPECULATIVE GATHER: w[t] is loaded for every item right after
// the text load, so the ~250cyc L2 gather latency overlaps the whole smem
// dedup sequence instead of trailing it (R7 profile: L1 27%, issue 24% —
// stall-bound, gathers serialized behind 5 barriers). Dups (~2.3%) waste a
// gather, then get multiplied out. (b) THIRD race level before the exact scan:
// each race phase overwrites the slot it later reads (no stale reads), so
// unresolved probability after L3 ~1e-4/block — the ~6000cyc scan tail that
// hit ~9% of blocks is gone. Cost: 2 extra barriers.

#define SEQ    200
#define BATCH  4096
#define DOCS   8
#define NTHR   512
#define NITEM  (SEQ * DOCS)       // 1600
#define HBITS  12
#define HSIZE  (1 << HBITS)       // 4096 slots per doc

__global__ __launch_bounds__(NTHR, 4)
void MNB_24111946400019_kernel(const int* __restrict__ text,
                               const float* __restrict__ w,
                               const float* __restrict__ bias,
                               float* __restrict__ out)
{
    __shared__ int           toks[DOCS * SEQ];
    __shared__ unsigned char marker[DOCS * HSIZE];      // 32KB
    __shared__ float         part[DOCS][17];

    const int b0  = blockIdx.x * DOCS;
    const int tid = threadIdx.x;
    const int d   = tid & 7;                 // this thread's doc (512%8==0)
    const int dt  = d * SEQ;
    const int dm  = d * HSIZE;

    // Load text (coalesced: item i=s*8+d -> 32B per 8 lanes) and immediately
    // issue the speculative weight gathers; their latency hides under dedup.
    int   tt[4];
    float wv[4];
    #pragma unroll
    for (int k = 0; k < 4; ++k) {
        const int i = tid + k * NTHR;
        const int s = i >> 3;
        tt[k] = (i < NITEM) ? text[s * BATCH + b0 + d] : 0;   // 0 = safe dummy
    }
    #pragma unroll
    for (int k = 0; k < 4; ++k) wv[k] = __ldg(&w[tt[k]]);     // in flight now

    // Init markers to 0xFF (seq idx 0..199 < 255): 2048 int4 stores.
    {
        int4* m4 = reinterpret_cast<int4*>(marker);
        const int4 ff = make_int4(-1, -1, -1, -1);
        #pragma unroll
        for (int k = 0; k < (DOCS * HSIZE / 16) / NTHR; ++k)
            m4[tid + k * NTHR] = ff;
    }
    #pragma unroll
    for (int k = 0; k < 4; ++k) {
        const int i = tid + k * NTHR;
        if (i < NITEM) toks[dt + (i >> 3)] = tt[k];
    }
    __syncthreads();

    int st[4];                               // 0=drop, 1=contribute, 2=unresolved
    unsigned hh[4];

    // ── Level 1 race ──
    #pragma unroll
    for (int k = 0; k < 4; ++k) {
        const int i = tid + k * NTHR;
        hh[k] = ((unsigned)tt[k] * 2654435761u) >> (32 - HBITS);
        if (i < NITEM) marker[dm + hh[k]] = (unsigned char)(i >> 3);
    }
    __syncthreads();
    #pragma unroll
    for (int k = 0; k < 4; ++k) {
        st[k] = 0;
        const int i = tid + k * NTHR;
        if (i < NITEM) {
            const int m = marker[dm + hh[k]];      // a genuine L1 racer (we stored)
            if (toks[dt + m] == tt[k]) st[k] = (m == (i >> 3)) ? 1 : 0;
            else                       st[k] = 2;  // ~4.9/doc
        }
    }
    __syncthreads();

    // ── Level 2 race (h2) ──
    #pragma unroll
    for (int k = 0; k < 4; ++k) {
        hh[k] = ((unsigned)tt[k] * 0x85EBCA77u) >> (32 - HBITS);
        if (st[k] == 2) marker[dm + hh[k]] = (unsigned char)((tid + k * NTHR) >> 3);
    }
    __syncthreads();
    #pragma unroll
    for (int k = 0; k < 4; ++k) {
        if (st[k] == 2) {
            const int m = marker[dm + hh[k]];      // a genuine L2 racer
            if (toks[dt + m] == tt[k]) st[k] = (m == ((tid + k * NTHR) >> 3)) ? 1 : 0;
            else                       st[k] = 3;  // ~0.02/doc
        }
    }
    __syncthreads();

    // ── Level 3 race (h3) ──
    #pragma unroll
    for (int k = 0; k < 4; ++k) {
        hh[k] = ((unsigned)tt[k] * 0xC2B2AE3Du) >> (32 - HBITS);
        if (st[k] == 3) marker[dm + hh[k]] = (unsigned char)((tid + k * NTHR) >> 3);
    }
    __syncthreads();

    float v = 0.0f;
    #pragma unroll
    for (int k = 0; k < 4; ++k) {
        const int s = (tid + k * NTHR) >> 3;
        int c = st[k];
        if (c == 3) {
            const int m = marker[dm + hh[k]];      // a genuine L3 racer
            if (toks[dt + m] == tt[k]) {
                c = (m == s) ? 1 : 0;
            } else {
                // Level 4 (~1e-4 of blocks): exact first-occurrence scan.
                int f = 0;
                while (toks[dt + f] != tt[k]) ++f;
                c = (f == s) ? 1 : 0;
            }
        }
        if (c == 1) v += wv[k];
    }

    // ── Per-doc reduction: fold lanes with equal (lane&7) ──
    v += __shfl_xor_sync(0xffffffffu, v, 16);
    v += __shfl_xor_sync(0xffffffffu, v, 8);
    if ((tid & 31) < 8) part[d][tid >> 5] = v;           // 16 warps
    __syncthreads();

    if (tid < 128) {
        const int dd = tid >> 4;
        const int j  = tid & 15;
        float s = part[dd][j];
        s += __shfl_xor_sync(0xffffffffu, s, 8);
        s += __shfl_xor_sync(0xffffffffu, s, 4);
        s += __shfl_xor_sync(0xffffffffu, s, 2);
        s += __shfl_xor_sync(0xffffffffu, s, 1);
        if (j == 0) out[b0 + dd] = s + bias[0];
    }
}

extern "C" void kernel_launch(void* const* d_in, const int* in_sizes, int n_in,
                              void* d_out, int out_size)
{
    const int*   text = (const int*)d_in[0];
    const float* w    = (const float*)d_in[1];
    const float* bias = (const float*)d_in[2];
    float*       out  = (float*)d_out;

    MNB_24111946400019_kernel<<<BATCH / DOCS, NTHR>>>(text, w, bias, out);
}

// round 9
// speedup vs baseline: 1.4060x; 1.0239x over previous
#include <cuda_runtime.h>
#include <cuda_bf16.h>

// text [SEQ=200, BATCH=4096] int32 (row-major text[s*BATCH+b]),
// w [V=50000] f32, bias [1] f32.  out[b] = sum_{unique t in doc b} w[t] + bias.
//
// R9: R8 was tail-bound, not latency-bound: grid 512 = 3.46 blocks/SM single
// wave -> 4-vs-3 block imbalance (~14%) + occ 79%. Re-grain to DOCS=4 /
// NTHR=256 / grid=1024 (6.92 blocks/SM, ~1% imbalance, 8 resident blocks/SM)
// and shrink per-doc hash tables to 2048 slots (8KB/block; collision cascade
// L1~9.8/doc -> L2~0.02/doc -> L3~1e-5 -> exact scan ~never, kept for
// correctness). Speculative gather + 3-level byte race retained from R8.

#define SEQ    200
#define BATCH  4096
#define DOCS   4
#define NTHR   256
#define NITEM  (SEQ * DOCS)       // 800
#define HBITS  11
#define HSIZE  (1 << HBITS)       // 2048 slots per doc

__global__ __launch_bounds__(NTHR, 8)
void MNB_24111946400019_kernel(const int* __restrict__ text,
                               const float* __restrict__ w,
                               const float* __restrict__ bias,
                               float* __restrict__ out)
{
    __shared__ int           toks[DOCS * SEQ];          // 3.2KB
    __shared__ unsigned char marker[DOCS * HSIZE];      // 8KB
    __shared__ float         part[DOCS][9];

    const int b0  = blockIdx.x * DOCS;
    const int tid = threadIdx.x;
    const int d   = tid & 3;                 // this thread's doc (256%4==0)
    const int dt  = d * SEQ;
    const int dm  = d * HSIZE;

    // Text load (item i=s*4+d: 4 lanes per 16B sector) + speculative gathers
    // issued immediately so L2 latency hides under the whole dedup sequence.
    int   tt[4];
    float wv[4];
    #pragma unroll
    for (int k = 0; k < 4; ++k) {
        const int i = tid + k * NTHR;
        const int s = i >> 2;
        tt[k] = (i < NITEM) ? __ldg(&text[s * BATCH + b0 + d]) : 0;
    }
    #pragma unroll
    for (int k = 0; k < 4; ++k) wv[k] = __ldg(&w[tt[k]]);     // in flight

    // Init markers to 0xFF (seq idx 0..199 < 255): 512 int4 stores.
    {
        int4* m4 = reinterpret_cast<int4*>(marker);
        const int4 ff = make_int4(-1, -1, -1, -1);
        m4[tid]        = ff;
        m4[tid + NTHR] = ff;
    }
    #pragma unroll
    for (int k = 0; k < 4; ++k) {
        const int i = tid + k * NTHR;
        if (i < NITEM) toks[dt + (i >> 2)] = tt[k];
    }
    __syncthreads();

    int st[4];                               // 0=drop, 1=contribute, 2/3=unresolved
    unsigned hh[4];

    // ── Level 1 race ──
    #pragma unroll
    for (int k = 0; k < 4; ++k) {
        const int i = tid + k * NTHR;
        hh[k] = ((unsigned)tt[k] * 2654435761u) >> (32 - HBITS);
        if (i < NITEM) marker[dm + hh[k]] = (unsigned char)(i >> 2);
    }
    __syncthreads();
    #pragma unroll
    for (int k = 0; k < 4; ++k) {
        st[k] = 0;
        const int i = tid + k * NTHR;
        if (i < NITEM) {
            const int m = marker[dm + hh[k]];      // genuine same-phase racer
            if (toks[dt + m] == tt[k]) st[k] = (m == (i >> 2)) ? 1 : 0;
            else                       st[k] = 2;  // ~9.8/doc
        }
    }
    __syncthreads();

    // ── Level 2 race (h2) ──
    #pragma unroll
    for (int k = 0; k < 4; ++k) {
        hh[k] = ((unsigned)tt[k] * 0x85EBCA77u) >> (32 - HBITS);
        if (st[k] == 2) marker[dm + hh[k]] = (unsigned char)((tid + k * NTHR) >> 2);
    }
    __syncthreads();
    #pragma unroll
    for (int k = 0; k < 4; ++k) {
        if (st[k] == 2) {
            const int m = marker[dm + hh[k]];
            if (toks[dt + m] == tt[k]) st[k] = (m == ((tid + k * NTHR) >> 2)) ? 1 : 0;
            else                       st[k] = 3;  // ~0.02/doc
        }
    }
    __syncthreads();

    // ── Level 3 race (h3) ──
    #pragma unroll
    for (int k = 0; k < 4; ++k) {
        hh[k] = ((unsigned)tt[k] * 0xC2B2AE3Du) >> (32 - HBITS);
        if (st[k] == 3) marker[dm + hh[k]] = (unsigned char)((tid + k * NTHR) >> 2);
    }
    __syncthreads();

    float v = 0.0f;
    #pragma unroll
    for (int k = 0; k < 4; ++k) {
        const int s = (tid + k * NTHR) >> 2;
        int c = st[k];
        if (c == 3) {
            const int m = marker[dm + hh[k]];
            if (toks[dt + m] == tt[k]) {
                c = (m == s) ? 1 : 0;
            } else {
                // Level 4 (~1e-5/doc): exact first-occurrence scan.
                int f = 0;
                while (toks[dt + f] != tt[k]) ++f;
                c = (f == s) ? 1 : 0;
            }
        }
        if (c == 1) v += wv[k];
    }

    // ── Per-doc reduction: lanes with equal (lane&3) share a doc ──
    v += __shfl_xor_sync(0xffffffffu, v, 16);
    v += __shfl_xor_sync(0xffffffffu, v, 8);
    v += __shfl_xor_sync(0xffffffffu, v, 4);
    if ((tid & 31) < 4) part[d][tid >> 5] = v;           // 8 warps
    __syncthreads();

    if (tid < 32) {
        const int dd = tid >> 3;                         // doc 0..3
        const int j  = tid & 7;                          // warp slot
        float s = part[dd][j];
        s += __shfl_xor_sync(0xffffffffu, s, 4);
        s += __shfl_xor_sync(0xffffffffu, s, 2);
        s += __shfl_xor_sync(0xffffffffu, s, 1);
        if (j == 0) out[b0 + dd] = s + bias[0];
    }
}

extern "C" void kernel_launch(void* const* d_in, const int* in_sizes, int n_in,
                              void* d_out, int out_size)
{
    const int*   text = (const int*)d_in[0];
    const float* w    = (const float*)d_in[1];
    const float* bias = (const float*)d_in[2];
    float*       out  = (float*)d_out;

    MNB_24111946400019_kernel<<<BATCH / DOCS, NTHR>>>(text, w, bias, out);
}